// round 1
// baseline (speedup 1.0000x reference)
#include <cuda_runtime.h>
#include <cuda_bf16.h>
#include <cstdint>

#define NRELM 20000
#define NEDGEM 640000

// Scratch (allocation-free rule: __device__ globals)
__device__ float g_Ph[NRELM * 128];
__device__ float g_Pt[NRELM * 128];
__device__ float g_M [NRELM * 128];
__device__ float g_av[(size_t)NEDGEM * 8];
__device__ float g_ss[NRELM * 8];
__device__ int   g_is64;

__device__ __forceinline__ float lrelu(float x) {
    return x >= 0.f ? x : 0.2f * x;
}

// Detect whether triplets are int64 (all high 32-bit words zero) or int32.
__global__ void k_detect(const int* __restrict__ t) {
    if (threadIdx.x == 0) {
        int any = 0;
        #pragma unroll 8
        for (int k = 0; k < 256; k++) any |= t[2 * k + 1];
        g_is64 = (any == 0) ? 1 : 0;
    }
}

// Zero out and seg_sum (out is poisoned by harness; graph replays accumulate via red)
__global__ void k_zero(float* __restrict__ out, int nrel) {
    int i = blockIdx.x * blockDim.x + threadIdx.x;
    int ntot = nrel * 128;
    if (i < ntot) out[i] = 0.f;
    if (i < nrel * 8) g_ss[i] = 0.f;
}

// Precompute Ph, Pt(+b), M(+b): per-relation projections.
// Block: 128 threads (one output column each), RPB relations per block.
#define RPB 8
__global__ void k_pre(const float* __restrict__ emb,
                      const float* __restrict__ wA, const float* __restrict__ bA,
                      const float* __restrict__ wG, const float* __restrict__ bG,
                      int nrel) {
    __shared__ float se[RPB * 128];
    const int r0 = blockIdx.x * RPB;
    const int t = threadIdx.x;  // 0..127 output dim

    #pragma unroll
    for (int i = 0; i < RPB; i++) {
        int r = r0 + i;
        se[i * 128 + t] = (r < nrel) ? emb[(size_t)r * 128 + t] : 0.f;
    }
    __syncthreads();

    float ah[RPB], at[RPB], am[RPB];
    #pragma unroll
    for (int i = 0; i < RPB; i++) { ah[i] = 0.f; at[i] = 0.f; am[i] = 0.f; }

    const float* wh = wA + (size_t)t * 256;
    const float* wt = wh + 128;
    const float* wg = wG + (size_t)t * 128;

    #pragma unroll 4
    for (int d = 0; d < 128; d += 4) {
        float4 h4 = *(const float4*)(wh + d);
        float4 t4 = *(const float4*)(wt + d);
        float4 g4 = *(const float4*)(wg + d);
        #pragma unroll
        for (int i = 0; i < RPB; i++) {
            float e0 = se[i * 128 + d + 0];
            float e1 = se[i * 128 + d + 1];
            float e2 = se[i * 128 + d + 2];
            float e3 = se[i * 128 + d + 3];
            ah[i] = fmaf(e0, h4.x, fmaf(e1, h4.y, fmaf(e2, h4.z, fmaf(e3, h4.w, ah[i]))));
            at[i] = fmaf(e0, t4.x, fmaf(e1, t4.y, fmaf(e2, t4.z, fmaf(e3, t4.w, at[i]))));
            am[i] = fmaf(e0, g4.x, fmaf(e1, g4.y, fmaf(e2, g4.z, fmaf(e3, g4.w, am[i]))));
        }
    }

    float bb = bA[t];
    float bg = bG[t];
    #pragma unroll
    for (int i = 0; i < RPB; i++) {
        int r = r0 + i;
        if (r < nrel) {
            g_Ph[(size_t)r * 128 + t] = ah[i];
            g_Pt[(size_t)r * 128 + t] = at[i] + bb;
            g_M [(size_t)r * 128 + t] = am[i] + bg;
        }
    }
}

// Pass A: per-edge attention logits -> exp -> scratch + segment sum.
// One warp per edge; lane l covers dims 4l..4l+3 (head = l>>2).
__global__ void k_attn(const void* __restrict__ trip,
                       const float* __restrict__ attn_bin,
                       const float* __restrict__ attn_vec,
                       int nedge) {
    const int lane = threadIdx.x & 31;
    const int warp = (blockIdx.x * blockDim.x + threadIdx.x) >> 5;
    const int nw = (gridDim.x * blockDim.x) >> 5;
    const int is64 = g_is64;

    // attn_vec flat [h*16 + dd]; lane l covers flat[4l..4l+3]
    const float4 vec4 = *(const float4*)(attn_vec + 4 * lane);

    for (int e = warp; e < nedge; e += nw) {
        int h = 0, tl = 0, bn = 0;
        if (lane == 0) {
            if (is64) {
                const long long* T = (const long long*)trip;
                h  = (int)T[(size_t)3 * e];
                tl = (int)T[(size_t)3 * e + 1];
                bn = (int)T[(size_t)3 * e + 2];
            } else {
                const int* T = (const int*)trip;
                h  = T[(size_t)3 * e];
                tl = T[(size_t)3 * e + 1];
                bn = T[(size_t)3 * e + 2];
            }
        }
        h  = __shfl_sync(0xffffffffu, h, 0);
        tl = __shfl_sync(0xffffffffu, tl, 0);
        bn = __shfl_sync(0xffffffffu, bn, 0);

        float4 p = *(const float4*)(g_Ph + (size_t)h  * 128 + 4 * lane);
        float4 q = *(const float4*)(g_Pt + (size_t)tl * 128 + 4 * lane);
        float x0 = lrelu(p.x + q.x);
        float x1 = lrelu(p.y + q.y);
        float x2 = lrelu(p.z + q.z);
        float x3 = lrelu(p.w + q.w);
        float s = fmaf(x0, vec4.x, fmaf(x1, vec4.y, fmaf(x2, vec4.z, x3 * vec4.w)));
        // reduce within 4-lane head group
        s += __shfl_xor_sync(0xffffffffu, s, 1);
        s += __shfl_xor_sync(0xffffffffu, s, 2);
        // lane l<8 takes head l's value from lane 4l
        float a = __shfl_sync(0xffffffffu, s, (lane & 7) * 4);
        if (lane < 8) {
            float b = attn_bin[bn * 8 + lane];
            b = (b >= 0.f) ? b : 0.2f * b;
            float v = __expf(a + b);
            g_av[(size_t)e * 8 + lane] = v;
            atomicAdd(&g_ss[h * 8 + lane], v);
        }
    }
}

// Pass B: beta * msg scattered into out via vectorized red.global
__global__ void k_aggr(const void* __restrict__ trip,
                       float* __restrict__ out,
                       int nedge) {
    const int lane = threadIdx.x & 31;
    const int warp = (blockIdx.x * blockDim.x + threadIdx.x) >> 5;
    const int nw = (gridDim.x * blockDim.x) >> 5;
    const int is64 = g_is64;

    for (int e = warp; e < nedge; e += nw) {
        int h = 0, tl = 0;
        if (lane == 0) {
            if (is64) {
                const long long* T = (const long long*)trip;
                h  = (int)T[(size_t)3 * e];
                tl = (int)T[(size_t)3 * e + 1];
            } else {
                const int* T = (const int*)trip;
                h  = T[(size_t)3 * e];
                tl = T[(size_t)3 * e + 1];
            }
        }
        h  = __shfl_sync(0xffffffffu, h, 0);
        tl = __shfl_sync(0xffffffffu, tl, 0);

        const int hh = lane >> 2;
        float v = g_av[(size_t)e * 8 + hh];
        float s = g_ss[h * 8 + hh];
        float beta = v / (s + 1e-16f);

        float4 m = *(const float4*)(g_M + (size_t)tl * 128 + 4 * lane);
        float* p = out + (size_t)h * 128 + 4 * lane;
        size_t gp = __cvta_generic_to_global(p);
        asm volatile("red.global.add.v4.f32 [%0], {%1, %2, %3, %4};"
                     :: "l"(gp), "f"(beta * m.x), "f"(beta * m.y),
                        "f"(beta * m.z), "f"(beta * m.w)
                     : "memory");
    }
}

extern "C" void kernel_launch(void* const* d_in, const int* in_sizes, int n_in,
                              void* d_out, int out_size) {
    const float* emb = (const float*)d_in[0];
    const void*  trip = d_in[1];
    const float* wA  = (const float*)d_in[2];
    const float* bA  = (const float*)d_in[3];
    const float* bin = (const float*)d_in[4];
    const float* vec = (const float*)d_in[5];
    const float* wG  = (const float*)d_in[6];
    const float* bG  = (const float*)d_in[7];
    float* out = (float*)d_out;

    int nrel  = in_sizes[0] / 128;
    int nedge = in_sizes[1] / 3;

    k_detect<<<1, 32>>>((const int*)trip);
    {
        int n = nrel * 128;
        k_zero<<<(n + 255) / 256, 256>>>(out, nrel);
    }
    k_pre<<<(nrel + RPB - 1) / RPB, 128>>>(emb, wA, bA, wG, bG, nrel);
    k_attn<<<4096, 256>>>(trip, bin, vec, nedge);
    k_aggr<<<4096, 256>>>(trip, out, nedge);
}